// round 6
// baseline (speedup 1.0000x reference)
#include <cuda_runtime.h>

#define N_NODES 100000
#define N_EDGES 1600000
// feature widths: 128 -> 128 -> 128 -> 64
#define F128 128
#define F64  64

// ---------------- scratch (device globals; no allocation allowed) ----------
__device__ int   g_deg_out[N_NODES];
__device__ int   g_deg_in[N_NODES];
__device__ float g_norm_src[N_NODES];
__device__ float g_norm_dst[N_NODES];
__device__ int   g_row_start[N_NODES + 1];
__device__ int   g_cursor[N_NODES];
__device__ int   g_esrc[N_EDGES];
__device__ float g_t[N_NODES * 128];   // post-GEMM buffer (scatter source)
__device__ float g_h[N_NODES * 128];   // hidden activations
__device__ int   g_block_sums[128];
__device__ int   g_block_offs[128];

// ---------------- degree / norm -------------------------------------------
__global__ void zero_deg_kernel() {
    int i = blockIdx.x * blockDim.x + threadIdx.x;
    if (i < N_NODES) { g_deg_out[i] = 0; g_deg_in[i] = 0; }
}

__global__ void count_deg_kernel(const int* __restrict__ src, const int* __restrict__ dst) {
    int e = blockIdx.x * blockDim.x + threadIdx.x;
    if (e < N_EDGES) {
        atomicAdd(&g_deg_out[src[e]], 1);
        atomicAdd(&g_deg_in[dst[e]], 1);
    }
}

__global__ void norms_kernel() {
    int i = blockIdx.x * blockDim.x + threadIdx.x;
    if (i < N_NODES) {
        float dout = (float)max(g_deg_out[i], 1);
        float din  = (float)max(g_deg_in[i], 1);
        g_norm_src[i] = rsqrtf(dout);
        g_norm_dst[i] = rsqrtf(din);
    }
}

// ---------------- CSR build (exclusive scan of deg_in) ---------------------
__global__ void scan1_kernel() {
    __shared__ int sh[1024];
    int tid = threadIdx.x;
    int i = blockIdx.x * 1024 + tid;
    int v = (i < N_NODES) ? g_deg_in[i] : 0;
    sh[tid] = v;
    __syncthreads();
    for (int off = 1; off < 1024; off <<= 1) {
        int x = (tid >= off) ? sh[tid - off] : 0;
        __syncthreads();
        sh[tid] += x;
        __syncthreads();
    }
    if (i < N_NODES) g_row_start[i] = sh[tid] - v;  // local exclusive
    if (tid == 1023) g_block_sums[blockIdx.x] = sh[1023];
}

__global__ void scan2_kernel(int nblocks) {
    __shared__ int sh[128];
    int tid = threadIdx.x;
    int v = (tid < nblocks) ? g_block_sums[tid] : 0;
    sh[tid] = v;
    __syncthreads();
    for (int off = 1; off < 128; off <<= 1) {
        int x = (tid >= off) ? sh[tid - off] : 0;
        __syncthreads();
        sh[tid] += x;
        __syncthreads();
    }
    if (tid < nblocks) g_block_offs[tid] = sh[tid] - v;  // exclusive
}

__global__ void scan3_kernel() {
    int i = blockIdx.x * blockDim.x + threadIdx.x;
    if (i < N_NODES) {
        int rs = g_row_start[i] + g_block_offs[i >> 10];
        g_row_start[i] = rs;
        g_cursor[i] = rs;
        if (i == 0) g_row_start[N_NODES] = N_EDGES;
    }
}

__global__ void csr_fill_kernel(const int* __restrict__ src, const int* __restrict__ dst) {
    int e = blockIdx.x * blockDim.x + threadIdx.x;
    if (e < N_EDGES) {
        int p = atomicAdd(&g_cursor[dst[e]], 1);
        g_esrc[p] = src[e];
    }
}

// ---------------- GEMM: C[r][n] = norm_src[r] * sum_k A[r][k] * W[k][n] ----
// A: [N,128] row-major. W: [128,BN] row-major. C: [N,BN].
template <int BN>
__global__ __launch_bounds__(256) void gemm_kernel(
    const float* __restrict__ A, const float* __restrict__ W,
    float* __restrict__ C)
{
    const int BM = 64, BK = 16, TM = 8;
    const int TN = BN / 32;
    __shared__ float As[BK][BM + 4];
    __shared__ float Ws[BK][BN];

    int tid = threadIdx.x;
    int tx = tid & 31;       // 0..31 (col groups)
    int ty = tid >> 5;       // 0..7  (row groups)
    int rowBase = blockIdx.x * BM;

    float acc[TM][TN];
#pragma unroll
    for (int i = 0; i < TM; i++)
#pragma unroll
        for (int j = 0; j < TN; j++) acc[i][j] = 0.0f;

    for (int kk = 0; kk < 128; kk += BK) {
        // A tile: 64 rows x 16 k, one float4 per thread (along k)
        {
            int r = tid >> 2;            // 0..63
            int kq = (tid & 3) << 2;     // 0,4,8,12
            int grow = rowBase + r;
            float4 v = make_float4(0.f, 0.f, 0.f, 0.f);
            if (grow < N_NODES) v = *(const float4*)(A + (long)grow * 128 + kk + kq);
            As[kq + 0][r] = v.x; As[kq + 1][r] = v.y;
            As[kq + 2][r] = v.z; As[kq + 3][r] = v.w;
        }
        // W tile: 16 x BN
        for (int i = tid; i < BK * BN; i += 256) {
            int k = i / BN, n = i % BN;
            Ws[k][n] = W[(kk + k) * BN + n];
        }
        __syncthreads();

#pragma unroll
        for (int k = 0; k < BK; k++) {
            float a[TM], w[TN];
#pragma unroll
            for (int i = 0; i < TM; i++) a[i] = As[k][ty * TM + i];
#pragma unroll
            for (int j = 0; j < TN; j++) w[j] = Ws[k][tx + 32 * j];
#pragma unroll
            for (int i = 0; i < TM; i++)
#pragma unroll
                for (int j = 0; j < TN; j++)
                    acc[i][j] += a[i] * w[j];
        }
        __syncthreads();
    }

#pragma unroll
    for (int i = 0; i < TM; i++) {
        int r = rowBase + ty * TM + i;
        if (r < N_NODES) {
            float s = g_norm_src[r];
#pragma unroll
            for (int j = 0; j < TN; j++)
                C[(long)r * BN + tx + 32 * j] = acc[i][j] * s;
        }
    }
}

// ---------------- Gather-aggregate + epilogue ------------------------------
// out[v] = act( norm_dst[v] * sum_{e in in(v)} t[esrc[e]] + b )
// FPL = floats per lane (4 for 128-wide, 2 for 64-wide). Warp per node.
template <int FPL, bool RELU>
__global__ __launch_bounds__(256) void gather_kernel(
    const float* __restrict__ t, const float* __restrict__ bias,
    float* __restrict__ out)
{
    int warp = (blockIdx.x * blockDim.x + threadIdx.x) >> 5;
    int lane = threadIdx.x & 31;
    if (warp >= N_NODES) return;

    const int W = FPL * 32;
    int beg = g_row_start[warp];
    int end = g_row_start[warp + 1];

    float acc[FPL];
#pragma unroll
    for (int q = 0; q < FPL; q++) acc[q] = 0.0f;

    for (int base = beg; base < end; base += 32) {
        int cnt = min(32, end - base);
        int eid = 0;
        if (base + lane < end) eid = g_esrc[base + lane];
        for (int j = 0; j < cnt; j++) {
            int s = __shfl_sync(0xffffffffu, eid, j);
            if (FPL == 4) {
                float4 v = *(const float4*)(t + (long)s * W + lane * 4);
                acc[0] += v.x; acc[1] += v.y; acc[2] += v.z; acc[3] += v.w;
            } else {
                float2 v = *(const float2*)(t + (long)s * W + lane * 2);
                acc[0] += v.x; acc[1] += v.y;
            }
        }
    }

    float nd = g_norm_dst[warp];
    float r[FPL];
#pragma unroll
    for (int q = 0; q < FPL; q++) {
        r[q] = acc[q] * nd + bias[lane * FPL + q];
        if (RELU) r[q] = fmaxf(r[q], 0.0f);
    }
    if (FPL == 4) {
        *(float4*)(out + (long)warp * W + lane * 4) = make_float4(r[0], r[1], r[2], r[3]);
    } else {
        *(float2*)(out + (long)warp * W + lane * 2) = make_float2(r[0], r[1]);
    }
}

// ---------------- launch ---------------------------------------------------
extern "C" void kernel_launch(void* const* d_in, const int* in_sizes, int n_in,
                              void* d_out, int out_size)
{
    const float* feat = (const float*)d_in[0];
    const int*   src  = (const int*)d_in[1];
    const int*   dst  = (const int*)d_in[2];
    const float* W0   = (const float*)d_in[3];
    const float* b0   = (const float*)d_in[4];
    const float* W1   = (const float*)d_in[5];
    const float* b1   = (const float*)d_in[6];
    const float* W2   = (const float*)d_in[7];
    const float* b2   = (const float*)d_in[8];
    float* out = (float*)d_out;

    float *t_ptr, *h_ptr;
    cudaGetSymbolAddress((void**)&t_ptr, g_t);
    cudaGetSymbolAddress((void**)&h_ptr, g_h);

    const int TB = 256;
    int nodeBlocks = (N_NODES + TB - 1) / TB;       // 391
    int edgeBlocks = (N_EDGES + TB - 1) / TB;       // 6250
    int scanBlocks = (N_NODES + 1023) / 1024;       // 98
    int gemmBlocks = (N_NODES + 63) / 64;           // 1563
    int gatherBlocks = (N_NODES + 7) / 8;           // 12500 (8 warps / block)

    // degrees + norms
    zero_deg_kernel<<<nodeBlocks, TB>>>();
    count_deg_kernel<<<edgeBlocks, TB>>>(src, dst);
    norms_kernel<<<nodeBlocks, TB>>>();

    // CSR by dst
    scan1_kernel<<<scanBlocks, 1024>>>();
    scan2_kernel<<<1, 128>>>(scanBlocks);
    scan3_kernel<<<nodeBlocks, TB>>>();
    csr_fill_kernel<<<edgeBlocks, TB>>>(src, dst);

    // layer 0: feat(128) -> h(128), relu
    gemm_kernel<128><<<gemmBlocks, TB>>>(feat, W0, t_ptr);
    gather_kernel<4, true><<<gatherBlocks, TB>>>(t_ptr, b0, h_ptr);

    // layer 1: h(128) -> h(128), relu  (t buffer reused; gather reads t, writes h)
    gemm_kernel<128><<<gemmBlocks, TB>>>(h_ptr, W1, t_ptr);
    gather_kernel<4, true><<<gatherBlocks, TB>>>(t_ptr, b1, h_ptr);

    // layer 2: h(128) -> out(64), no relu
    gemm_kernel<64><<<gemmBlocks, TB>>>(h_ptr, W2, t_ptr);
    gather_kernel<2, false><<<gatherBlocks, TB>>>(t_ptr, b2, out);
}

// round 10
// speedup vs baseline: 1.2865x; 1.2865x over previous
#include <cuda_runtime.h>
#include <cstdint>

#define N_NODES 100000
#define N_EDGES 1600000

// ---------------- scratch (device globals; no allocation allowed) ----------
__device__ int   g_deg_out[N_NODES];
__device__ int   g_deg_in[N_NODES];
__device__ float g_norm_src[N_NODES];
__device__ float g_norm_dst[N_NODES];
__device__ int   g_row_start[N_NODES + 1];
__device__ int   g_cursor[N_NODES];
__device__ int   g_esrc[N_EDGES];
__device__ float g_t[N_NODES * 128];   // post-GEMM buffer (gather source)
__device__ float g_h[N_NODES * 128];   // hidden activations
__device__ int   g_block_sums[128];
__device__ int   g_block_offs[128];

// ---------------- degree / norm -------------------------------------------
__global__ void zero_deg_kernel() {
    int i = blockIdx.x * blockDim.x + threadIdx.x;
    if (i < N_NODES) { g_deg_out[i] = 0; g_deg_in[i] = 0; }
}

__global__ void count_deg_kernel(const int* __restrict__ src, const int* __restrict__ dst) {
    int e = blockIdx.x * blockDim.x + threadIdx.x;
    if (e < N_EDGES) {
        atomicAdd(&g_deg_out[src[e]], 1);
        atomicAdd(&g_deg_in[dst[e]], 1);
    }
}

__global__ void norms_kernel() {
    int i = blockIdx.x * blockDim.x + threadIdx.x;
    if (i < N_NODES) {
        float dout = (float)max(g_deg_out[i], 1);
        float din  = (float)max(g_deg_in[i], 1);
        g_norm_src[i] = rsqrtf(dout);
        g_norm_dst[i] = rsqrtf(din);
    }
}

// ---------------- CSR build (exclusive scan of deg_in) ---------------------
__global__ void scan1_kernel() {
    __shared__ int sh[1024];
    int tid = threadIdx.x;
    int i = blockIdx.x * 1024 + tid;
    int v = (i < N_NODES) ? g_deg_in[i] : 0;
    sh[tid] = v;
    __syncthreads();
    for (int off = 1; off < 1024; off <<= 1) {
        int x = (tid >= off) ? sh[tid - off] : 0;
        __syncthreads();
        sh[tid] += x;
        __syncthreads();
    }
    if (i < N_NODES) g_row_start[i] = sh[tid] - v;  // local exclusive
    if (tid == 1023) g_block_sums[blockIdx.x] = sh[1023];
}

__global__ void scan2_kernel(int nblocks) {
    __shared__ int sh[128];
    int tid = threadIdx.x;
    int v = (tid < nblocks) ? g_block_sums[tid] : 0;
    sh[tid] = v;
    __syncthreads();
    for (int off = 1; off < 128; off <<= 1) {
        int x = (tid >= off) ? sh[tid - off] : 0;
        __syncthreads();
        sh[tid] += x;
        __syncthreads();
    }
    if (tid < nblocks) g_block_offs[tid] = sh[tid] - v;  // exclusive
}

__global__ void scan3_kernel() {
    int i = blockIdx.x * blockDim.x + threadIdx.x;
    if (i < N_NODES) {
        int rs = g_row_start[i] + g_block_offs[i >> 10];
        g_row_start[i] = rs;
        g_cursor[i] = rs;
        if (i == 0) g_row_start[N_NODES] = N_EDGES;
    }
}

__global__ void csr_fill_kernel(const int* __restrict__ src, const int* __restrict__ dst) {
    int e = blockIdx.x * blockDim.x + threadIdx.x;
    if (e < N_EDGES) {
        int p = atomicAdd(&g_cursor[dst[e]], 1);
        g_esrc[p] = src[e];
    }
}

// ---------------- TF32 tensor-core GEMM ------------------------------------
// C[r][n] = norm_src[r] * sum_k A[r][k] * W[k][n]
// A: [N,128] row-major fp32. W: [128,BN] row-major fp32. C: [N,BN] fp32.
// Full K=128 staged in smem. A as [row][k] stride 132, W transposed [n][k]
// stride 132 -> both conflict-free for m16n8k8 fragment loads.

__device__ __forceinline__ uint32_t f2tf32(float x) {
    uint32_t r;
    asm("cvt.rna.tf32.f32 %0, %1;" : "=r"(r) : "f"(x));
    return r;
}

__device__ __forceinline__ void mma_tf32(float* d, const uint32_t* a, const uint32_t* b) {
    asm volatile(
        "mma.sync.aligned.m16n8k8.row.col.f32.tf32.tf32.f32 "
        "{%0,%1,%2,%3}, {%4,%5,%6,%7}, {%8,%9}, {%0,%1,%2,%3};\n"
        : "+f"(d[0]), "+f"(d[1]), "+f"(d[2]), "+f"(d[3])
        : "r"(a[0]), "r"(a[1]), "r"(a[2]), "r"(a[3]), "r"(b[0]), "r"(b[1]));
}

#define LDK 132  // padded k-stride (conflict-free: 132 % 32 == 4)

template <int BN>
__global__ __launch_bounds__(256, 1) void mma_gemm_kernel(
    const float* __restrict__ A, const float* __restrict__ W,
    float* __restrict__ C)
{
    extern __shared__ uint32_t smem[];
    uint32_t* As = smem;                 // [128][LDK]
    uint32_t* Ws = smem + 128 * LDK;     // [BN][LDK]

    const int tid = threadIdx.x;
    const int rowBase = blockIdx.x * 128;

    // --- stage A: 128 rows x 128 k (tf32-converted), coalesced float4 reads
    {
        const float4* A4 = (const float4*)A;
#pragma unroll
        for (int it = 0; it < 16; it++) {
            int f = tid + it * 256;            // float4 index within tile
            int r = f >> 5;                    // 32 float4 per row
            int c4 = (f & 31) << 2;
            int grow = rowBase + r;
            float4 v = make_float4(0.f, 0.f, 0.f, 0.f);
            if (grow < N_NODES) v = A4[(long)grow * 32 + (f & 31)];
            uint32_t* p = As + r * LDK + c4;
            p[0] = f2tf32(v.x); p[1] = f2tf32(v.y);
            p[2] = f2tf32(v.z); p[3] = f2tf32(v.w);
        }
    }
    // --- stage W transposed: Ws[n][k] = tf32(W[k][n])
    for (int e = tid; e < 128 * BN; e += 256) {
        int k = e / BN, n = e % BN;
        Ws[n * LDK + k] = f2tf32(W[k * BN + n]);
    }
    __syncthreads();

    const int lane = tid & 31;
    const int w = tid >> 5;
    const int warp_m = w & 3;            // 4 m-warps: 32 rows each
    const int warp_n = w >> 2;           // 2 n-warps
    const int HN = BN / 2;               // cols per warp (64 or 32)
    const int NT = HN / 8;               // n-subtiles (8 or 4)
    const int g = lane >> 2;
    const int t4 = lane & 3;

    float acc[2][8][4];                  // [m-subtile][n-subtile][frag] (NT<=8)
#pragma unroll
    for (int mi = 0; mi < 2; mi++)
#pragma unroll
        for (int ni = 0; ni < NT; ni++)
#pragma unroll
            for (int q = 0; q < 4; q++) acc[mi][ni][q] = 0.0f;

    const uint32_t* Abase = As + (warp_m * 32 + g) * LDK;
    const uint32_t* Bbase = Ws + (warp_n * HN + g) * LDK;

#pragma unroll
    for (int k8 = 0; k8 < 16; k8++) {
        const int kb = k8 * 8;
        uint32_t a[2][4];
#pragma unroll
        for (int mi = 0; mi < 2; mi++) {
            const uint32_t* p = Abase + mi * 16 * LDK + kb + t4;
            a[mi][0] = p[0];
            a[mi][1] = p[8 * LDK];
            a[mi][2] = p[4];
            a[mi][3] = p[8 * LDK + 4];
        }
        uint32_t b[8][2];
#pragma unroll
        for (int ni = 0; ni < NT; ni++) {
            const uint32_t* p = Bbase + ni * 8 * LDK + kb + t4;
            b[ni][0] = p[0];
            b[ni][1] = p[4];
        }
#pragma unroll
        for (int mi = 0; mi < 2; mi++)
#pragma unroll
            for (int ni = 0; ni < NT; ni++)
                mma_tf32(acc[mi][ni], a[mi], b[ni]);
    }

    // --- epilogue: scale by norm_src and store (float2 per frag half)
#pragma unroll
    for (int mi = 0; mi < 2; mi++) {
        int r0 = rowBase + warp_m * 32 + mi * 16 + g;
        int r1 = r0 + 8;
        float s0 = (r0 < N_NODES) ? g_norm_src[r0] : 0.0f;
        float s1 = (r1 < N_NODES) ? g_norm_src[r1] : 0.0f;
#pragma unroll
        for (int ni = 0; ni < NT; ni++) {
            int c = warp_n * HN + ni * 8 + 2 * t4;
            if (r0 < N_NODES)
                *(float2*)(C + (long)r0 * BN + c) =
                    make_float2(acc[mi][ni][0] * s0, acc[mi][ni][1] * s0);
            if (r1 < N_NODES)
                *(float2*)(C + (long)r1 * BN + c) =
                    make_float2(acc[mi][ni][2] * s1, acc[mi][ni][3] * s1);
        }
    }
}

// ---------------- Gather-aggregate + epilogue ------------------------------
// out[v] = act( norm_dst[v] * sum_{e in in(v)} t[esrc[e]] + b )
// FPL = floats per lane (4 for 128-wide, 2 for 64-wide). Warp per node.
template <int FPL, bool RELU>
__global__ __launch_bounds__(256) void gather_kernel(
    const float* __restrict__ t, const float* __restrict__ bias,
    float* __restrict__ out)
{
    int warp = (blockIdx.x * blockDim.x + threadIdx.x) >> 5;
    int lane = threadIdx.x & 31;
    if (warp >= N_NODES) return;

    const int W = FPL * 32;
    int beg = g_row_start[warp];
    int end = g_row_start[warp + 1];

    float acc[FPL];
#pragma unroll
    for (int q = 0; q < FPL; q++) acc[q] = 0.0f;

    for (int base = beg; base < end; base += 32) {
        int cnt = min(32, end - base);
        int eid = 0;
        if (base + lane < end) eid = g_esrc[base + lane];
        int j = 0;
        // unrolled-by-4 body: 4 independent row loads in flight
        for (; j + 4 <= cnt; j += 4) {
            int s0 = __shfl_sync(0xffffffffu, eid, j + 0);
            int s1 = __shfl_sync(0xffffffffu, eid, j + 1);
            int s2 = __shfl_sync(0xffffffffu, eid, j + 2);
            int s3 = __shfl_sync(0xffffffffu, eid, j + 3);
            if (FPL == 4) {
                float4 v0 = *(const float4*)(t + (long)s0 * W + lane * 4);
                float4 v1 = *(const float4*)(t + (long)s1 * W + lane * 4);
                float4 v2 = *(const float4*)(t + (long)s2 * W + lane * 4);
                float4 v3 = *(const float4*)(t + (long)s3 * W + lane * 4);
                acc[0] += v0.x + v1.x + v2.x + v3.x;
                acc[1] += v0.y + v1.y + v2.y + v3.y;
                acc[2] += v0.z + v1.z + v2.z + v3.z;
                acc[3] += v0.w + v1.w + v2.w + v3.w;
            } else {
                float2 v0 = *(const float2*)(t + (long)s0 * W + lane * 2);
                float2 v1 = *(const float2*)(t + (long)s1 * W + lane * 2);
                float2 v2 = *(const float2*)(t + (long)s2 * W + lane * 2);
                float2 v3 = *(const float2*)(t + (long)s3 * W + lane * 2);
                acc[0] += v0.x + v1.x + v2.x + v3.x;
                acc[1] += v0.y + v1.y + v2.y + v3.y;
            }
        }
        for (; j < cnt; j++) {
            int s = __shfl_sync(0xffffffffu, eid, j);
            if (FPL == 4) {
                float4 v = *(const float4*)(t + (long)s * W + lane * 4);
                acc[0] += v.x; acc[1] += v.y; acc[2] += v.z; acc[3] += v.w;
            } else {
                float2 v = *(const float2*)(t + (long)s * W + lane * 2);
                acc[0] += v.x; acc[1] += v.y;
            }
        }
    }

    float nd = g_norm_dst[warp];
    float r[FPL];
#pragma unroll
    for (int q = 0; q < FPL; q++) {
        r[q] = acc[q] * nd + bias[lane * FPL + q];
        if (RELU) r[q] = fmaxf(r[q], 0.0f);
    }
    if (FPL == 4) {
        *(float4*)(out + (long)warp * W + lane * 4) = make_float4(r[0], r[1], r[2], r[3]);
    } else {
        *(float2*)(out + (long)warp * W + lane * 2) = make_float2(r[0], r[1]);
    }
}

// ---------------- launch ---------------------------------------------------
extern "C" void kernel_launch(void* const* d_in, const int* in_sizes, int n_in,
                              void* d_out, int out_size)
{
    const float* feat = (const float*)d_in[0];
    const int*   src  = (const int*)d_in[1];
    const int*   dst  = (const int*)d_in[2];
    const float* W0   = (const float*)d_in[3];
    const float* b0   = (const float*)d_in[4];
    const float* W1   = (const float*)d_in[5];
    const float* b1   = (const float*)d_in[6];
    const float* W2   = (const float*)d_in[7];
    const float* b2   = (const float*)d_in[8];
    float* out = (float*)d_out;

    float *t_ptr, *h_ptr;
    cudaGetSymbolAddress((void**)&t_ptr, g_t);
    cudaGetSymbolAddress((void**)&h_ptr, g_h);

    const int SMEM128 = (128 * LDK + 128 * LDK) * 4;  // 135168
    const int SMEM64  = (128 * LDK +  64 * LDK) * 4;  // 101376
    cudaFuncSetAttribute(mma_gemm_kernel<128>,
                         cudaFuncAttributeMaxDynamicSharedMemorySize, SMEM128);
    cudaFuncSetAttribute(mma_gemm_kernel<64>,
                         cudaFuncAttributeMaxDynamicSharedMemorySize, SMEM64);

    const int TB = 256;
    int nodeBlocks = (N_NODES + TB - 1) / TB;       // 391
    int edgeBlocks = (N_EDGES + TB - 1) / TB;       // 6250
    int scanBlocks = (N_NODES + 1023) / 1024;       // 98
    int gemmBlocks = (N_NODES + 127) / 128;         // 782
    int gatherBlocks = (N_NODES + 7) / 8;           // 12500 (8 warps / block)

    // degrees + norms
    zero_deg_kernel<<<nodeBlocks, TB>>>();
    count_deg_kernel<<<edgeBlocks, TB>>>(src, dst);
    norms_kernel<<<nodeBlocks, TB>>>();

    // CSR by dst
    scan1_kernel<<<scanBlocks, 1024>>>();
    scan2_kernel<<<1, 128>>>(scanBlocks);
    scan3_kernel<<<nodeBlocks, TB>>>();
    csr_fill_kernel<<<edgeBlocks, TB>>>(src, dst);

    // layer 0: feat(128) -> h(128), relu
    mma_gemm_kernel<128><<<gemmBlocks, TB, SMEM128>>>(feat, W0, t_ptr);
    gather_kernel<4, true><<<gatherBlocks, TB>>>(t_ptr, b0, h_ptr);

    // layer 1: h(128) -> h(128), relu
    mma_gemm_kernel<128><<<gemmBlocks, TB, SMEM128>>>(h_ptr, W1, t_ptr);
    gather_kernel<4, true><<<gatherBlocks, TB>>>(t_ptr, b1, h_ptr);

    // layer 2: h(128) -> out(64), no relu
    mma_gemm_kernel<64><<<gemmBlocks, TB, SMEM64>>>(h_ptr, W2, t_ptr);
    gather_kernel<2, false><<<gatherBlocks, TB>>>(t_ptr, b2, out);
}

// round 11
// speedup vs baseline: 1.4632x; 1.1374x over previous
#include <cuda_runtime.h>
#include <cuda_fp16.h>
#include <cstdint>

#define N_NODES 100000
#define N_EDGES 1600000

// ---------------- scratch (device globals; no allocation allowed) ----------
__device__ int   g_deg_out[N_NODES];
__device__ int   g_deg_in[N_NODES];
__device__ float g_norm_src[N_NODES];
__device__ float g_norm_dst[N_NODES];
__device__ int   g_row_start[N_NODES + 1];
__device__ int   g_cursor[N_NODES];
__device__ int   g_esrc[N_EDGES];
__device__ float g_t[N_NODES * 128];   // post-GEMM buffer (reinterpreted as __half)
__device__ float g_h[N_NODES * 128];   // hidden activations (fp32, GEMM input)
__device__ int   g_block_sums[128];
__device__ int   g_block_offs[128];

// ---------------- degree / norm -------------------------------------------
__global__ void zero_deg_kernel() {
    int i = blockIdx.x * blockDim.x + threadIdx.x;
    if (i < N_NODES) { g_deg_out[i] = 0; g_deg_in[i] = 0; }
}

__global__ void count_deg_kernel(const int* __restrict__ src, const int* __restrict__ dst) {
    int e = blockIdx.x * blockDim.x + threadIdx.x;
    if (e < N_EDGES) {
        atomicAdd(&g_deg_out[src[e]], 1);
        atomicAdd(&g_deg_in[dst[e]], 1);
    }
}

__global__ void norms_kernel() {
    int i = blockIdx.x * blockDim.x + threadIdx.x;
    if (i < N_NODES) {
        float dout = (float)max(g_deg_out[i], 1);
        float din  = (float)max(g_deg_in[i], 1);
        g_norm_src[i] = rsqrtf(dout);
        g_norm_dst[i] = rsqrtf(din);
    }
}

// ---------------- CSR build (exclusive scan of deg_in) ---------------------
__global__ void scan1_kernel() {
    __shared__ int sh[1024];
    int tid = threadIdx.x;
    int i = blockIdx.x * 1024 + tid;
    int v = (i < N_NODES) ? g_deg_in[i] : 0;
    sh[tid] = v;
    __syncthreads();
    for (int off = 1; off < 1024; off <<= 1) {
        int x = (tid >= off) ? sh[tid - off] : 0;
        __syncthreads();
        sh[tid] += x;
        __syncthreads();
    }
    if (i < N_NODES) g_row_start[i] = sh[tid] - v;  // local exclusive
    if (tid == 1023) g_block_sums[blockIdx.x] = sh[1023];
}

__global__ void scan2_kernel(int nblocks) {
    __shared__ int sh[128];
    int tid = threadIdx.x;
    int v = (tid < nblocks) ? g_block_sums[tid] : 0;
    sh[tid] = v;
    __syncthreads();
    for (int off = 1; off < 128; off <<= 1) {
        int x = (tid >= off) ? sh[tid - off] : 0;
        __syncthreads();
        sh[tid] += x;
        __syncthreads();
    }
    if (tid < nblocks) g_block_offs[tid] = sh[tid] - v;  // exclusive
}

__global__ void scan3_kernel() {
    int i = blockIdx.x * blockDim.x + threadIdx.x;
    if (i < N_NODES) {
        int rs = g_row_start[i] + g_block_offs[i >> 10];
        g_row_start[i] = rs;
        g_cursor[i] = rs;
        if (i == 0) g_row_start[N_NODES] = N_EDGES;
    }
}

__global__ void csr_fill_kernel(const int* __restrict__ src, const int* __restrict__ dst) {
    int e = blockIdx.x * blockDim.x + threadIdx.x;
    if (e < N_EDGES) {
        int p = atomicAdd(&g_cursor[dst[e]], 1);
        g_esrc[p] = src[e];
    }
}

// ---------------- TF32 tensor-core GEMM, fp16 output ------------------------
// C16[r][n] = half( norm_src[r] * sum_k A[r][k] * W[k][n] )
// A staged [row][k] stride LDK=132 (a-frag banks 4g+t4: conflict-free).
// W staged ROW-MAJOR [k][n] stride LDN=BN+8 (LDN%32==8):
//   STS bank = n%32 (conflict-free), b-frag bank = 8*t4+g (conflict-free).

__device__ __forceinline__ uint32_t f2tf32(float x) {
    uint32_t r;
    asm("cvt.rna.tf32.f32 %0, %1;" : "=r"(r) : "f"(x));
    return r;
}

__device__ __forceinline__ void mma_tf32(float* d, const uint32_t* a, const uint32_t* b) {
    asm volatile(
        "mma.sync.aligned.m16n8k8.row.col.f32.tf32.tf32.f32 "
        "{%0,%1,%2,%3}, {%4,%5,%6,%7}, {%8,%9}, {%0,%1,%2,%3};\n"
        : "+f"(d[0]), "+f"(d[1]), "+f"(d[2]), "+f"(d[3])
        : "r"(a[0]), "r"(a[1]), "r"(a[2]), "r"(a[3]), "r"(b[0]), "r"(b[1]));
}

#define LDK 132

template <int BN>
__global__ __launch_bounds__(256, 1) void mma_gemm_kernel(
    const float* __restrict__ A, const float* __restrict__ W,
    __half* __restrict__ C)
{
    const int LDN = BN + 8;              // 136 or 72; LDN % 32 == 8
    extern __shared__ uint32_t smem[];
    uint32_t* As = smem;                 // [128][LDK]
    uint32_t* Ws = smem + 128 * LDK;     // [128][LDN] row-major (k-major)

    const int tid = threadIdx.x;
    const int rowBase = blockIdx.x * 128;

    // --- stage A: 128 rows x 128 k (tf32), coalesced float4, conflict-free STS
    {
        const float4* A4 = (const float4*)A;
#pragma unroll
        for (int it = 0; it < 16; it++) {
            int f = tid + it * 256;
            int r = f >> 5;
            int c4 = (f & 31) << 2;
            int grow = rowBase + r;
            float4 v = make_float4(0.f, 0.f, 0.f, 0.f);
            if (grow < N_NODES) v = A4[(long)grow * 32 + (f & 31)];
            uint32_t* p = As + r * LDK + c4;
            p[0] = f2tf32(v.x); p[1] = f2tf32(v.y);
            p[2] = f2tf32(v.z); p[3] = f2tf32(v.w);
        }
    }
    // --- stage W row-major: Ws[k][n] (coalesced LDG, conflict-free STS)
    for (int e = tid; e < 128 * BN; e += 256) {
        int k = e / BN, n = e % BN;
        Ws[k * LDN + n] = f2tf32(W[k * BN + n]);
    }
    __syncthreads();

    const int lane = tid & 31;
    const int w = tid >> 5;
    const int warp_m = w & 3;            // 4 m-warps: 32 rows each
    const int warp_n = w >> 2;           // 2 n-warps
    const int HN = BN / 2;               // cols per warp (64 or 32)
    const int NT = HN / 8;               // n-subtiles (8 or 4)
    const int g = lane >> 2;
    const int t4 = lane & 3;

    float acc[2][8][4];
#pragma unroll
    for (int mi = 0; mi < 2; mi++)
#pragma unroll
        for (int ni = 0; ni < NT; ni++)
#pragma unroll
            for (int q = 0; q < 4; q++) acc[mi][ni][q] = 0.0f;

    const uint32_t* Abase = As + (warp_m * 32 + g) * LDK;
    const uint32_t* Bcol = Ws + warp_n * HN + g;      // + (kb+t4)*LDN + ni*8

#pragma unroll
    for (int k8 = 0; k8 < 16; k8++) {
        const int kb = k8 * 8;
        uint32_t a[2][4];
#pragma unroll
        for (int mi = 0; mi < 2; mi++) {
            const uint32_t* p = Abase + mi * 16 * LDK + kb + t4;
            a[mi][0] = p[0];
            a[mi][1] = p[8 * LDK];
            a[mi][2] = p[4];
            a[mi][3] = p[8 * LDK + 4];
        }
        uint32_t b[8][2];
        const uint32_t* Brow = Bcol + (kb + t4) * LDN;
#pragma unroll
        for (int ni = 0; ni < NT; ni++) {
            b[ni][0] = Brow[ni * 8];
            b[ni][1] = Brow[4 * LDN + ni * 8];
        }
#pragma unroll
        for (int mi = 0; mi < 2; mi++)
#pragma unroll
            for (int ni = 0; ni < NT; ni++)
                mma_tf32(acc[mi][ni], a[mi], b[ni]);
    }

    // --- epilogue: scale by norm_src, convert to fp16, half2 stores
#pragma unroll
    for (int mi = 0; mi < 2; mi++) {
        int r0 = rowBase + warp_m * 32 + mi * 16 + g;
        int r1 = r0 + 8;
        float s0 = (r0 < N_NODES) ? g_norm_src[r0] : 0.0f;
        float s1 = (r1 < N_NODES) ? g_norm_src[r1] : 0.0f;
#pragma unroll
        for (int ni = 0; ni < NT; ni++) {
            int c = warp_n * HN + ni * 8 + 2 * t4;
            if (r0 < N_NODES)
                *(__half2*)(C + (long)r0 * BN + c) =
                    __floats2half2_rn(acc[mi][ni][0] * s0, acc[mi][ni][1] * s0);
            if (r1 < N_NODES)
                *(__half2*)(C + (long)r1 * BN + c) =
                    __floats2half2_rn(acc[mi][ni][2] * s1, acc[mi][ni][3] * s1);
        }
    }
}

// ---------------- Gather-aggregate (fp16 in, fp32 out) ---------------------
// out[v] = act( norm_dst[v] * sum_{e in in(v)} t[esrc[e]] + b )
// HPL = halfs per lane (4 for 128-wide, 2 for 64-wide). Warp per node.
template <int HPL, bool RELU>
__global__ __launch_bounds__(256) void gather_kernel(
    const __half* __restrict__ t, const float* __restrict__ bias,
    float* __restrict__ out)
{
    int warp = (blockIdx.x * blockDim.x + threadIdx.x) >> 5;
    int lane = threadIdx.x & 31;
    if (warp >= N_NODES) return;

    const int W = HPL * 32;
    int beg = g_row_start[warp];
    int end = g_row_start[warp + 1];

    float acc[HPL];
#pragma unroll
    for (int q = 0; q < HPL; q++) acc[q] = 0.0f;

    for (int base = beg; base < end; base += 32) {
        int cnt = min(32, end - base);
        int eid = 0;
        if (base + lane < end) eid = g_esrc[base + lane];
        int j = 0;
        for (; j + 4 <= cnt; j += 4) {
            int s0 = __shfl_sync(0xffffffffu, eid, j + 0);
            int s1 = __shfl_sync(0xffffffffu, eid, j + 1);
            int s2 = __shfl_sync(0xffffffffu, eid, j + 2);
            int s3 = __shfl_sync(0xffffffffu, eid, j + 3);
            if (HPL == 4) {
                uint2 v0 = *(const uint2*)(t + (long)s0 * W + lane * 4);
                uint2 v1 = *(const uint2*)(t + (long)s1 * W + lane * 4);
                uint2 v2 = *(const uint2*)(t + (long)s2 * W + lane * 4);
                uint2 v3 = *(const uint2*)(t + (long)s3 * W + lane * 4);
                float2 a0 = __half22float2(*(__half2*)&v0.x), b0 = __half22float2(*(__half2*)&v0.y);
                float2 a1 = __half22float2(*(__half2*)&v1.x), b1 = __half22float2(*(__half2*)&v1.y);
                float2 a2 = __half22float2(*(__half2*)&v2.x), b2 = __half22float2(*(__half2*)&v2.y);
                float2 a3 = __half22float2(*(__half2*)&v3.x), b3 = __half22float2(*(__half2*)&v3.y);
                acc[0] += a0.x + a1.x + a2.x + a3.x;
                acc[1] += a0.y + a1.y + a2.y + a3.y;
                acc[2] += b0.x + b1.x + b2.x + b3.x;
                acc[3] += b0.y + b1.y + b2.y + b3.y;
            } else {
                uint32_t v0 = *(const uint32_t*)(t + (long)s0 * W + lane * 2);
                uint32_t v1 = *(const uint32_t*)(t + (long)s1 * W + lane * 2);
                uint32_t v2 = *(const uint32_t*)(t + (long)s2 * W + lane * 2);
                uint32_t v3 = *(const uint32_t*)(t + (long)s3 * W + lane * 2);
                float2 a0 = __half22float2(*(__half2*)&v0);
                float2 a1 = __half22float2(*(__half2*)&v1);
                float2 a2 = __half22float2(*(__half2*)&v2);
                float2 a3 = __half22float2(*(__half2*)&v3);
                acc[0] += a0.x + a1.x + a2.x + a3.x;
                acc[1] += a0.y + a1.y + a2.y + a3.y;
            }
        }
        for (; j < cnt; j++) {
            int s = __shfl_sync(0xffffffffu, eid, j);
            if (HPL == 4) {
                uint2 v = *(const uint2*)(t + (long)s * W + lane * 4);
                float2 a = __half22float2(*(__half2*)&v.x);
                float2 b = __half22float2(*(__half2*)&v.y);
                acc[0] += a.x; acc[1] += a.y; acc[2] += b.x; acc[3] += b.y;
            } else {
                uint32_t v = *(const uint32_t*)(t + (long)s * W + lane * 2);
                float2 a = __half22float2(*(__half2*)&v);
                acc[0] += a.x; acc[1] += a.y;
            }
        }
    }

    float nd = g_norm_dst[warp];
    float r[HPL];
#pragma unroll
    for (int q = 0; q < HPL; q++) {
        r[q] = acc[q] * nd + bias[lane * HPL + q];
        if (RELU) r[q] = fmaxf(r[q], 0.0f);
    }
    if (HPL == 4) {
        *(float4*)(out + (long)warp * W + lane * 4) = make_float4(r[0], r[1], r[2], r[3]);
    } else {
        *(float2*)(out + (long)warp * W + lane * 2) = make_float2(r[0], r[1]);
    }
}

// ---------------- launch ---------------------------------------------------
extern "C" void kernel_launch(void* const* d_in, const int* in_sizes, int n_in,
                              void* d_out, int out_size)
{
    const float* feat = (const float*)d_in[0];
    const int*   src  = (const int*)d_in[1];
    const int*   dst  = (const int*)d_in[2];
    const float* W0   = (const float*)d_in[3];
    const float* b0   = (const float*)d_in[4];
    const float* W1   = (const float*)d_in[5];
    const float* b1   = (const float*)d_in[6];
    const float* W2   = (const float*)d_in[7];
    const float* b2   = (const float*)d_in[8];
    float* out = (float*)d_out;

    float *t_raw, *h_ptr;
    cudaGetSymbolAddress((void**)&t_raw, g_t);
    cudaGetSymbolAddress((void**)&h_ptr, g_h);
    __half* t16 = (__half*)t_raw;

    const int SMEM128 = (128 * LDK + 128 * (128 + 8)) * 4;  // 137216
    const int SMEM64  = (128 * LDK + 128 * (64 + 8)) * 4;   // 104448
    cudaFuncSetAttribute(mma_gemm_kernel<128>,
                         cudaFuncAttributeMaxDynamicSharedMemorySize, SMEM128);
    cudaFuncSetAttribute(mma_gemm_kernel<64>,
                         cudaFuncAttributeMaxDynamicSharedMemorySize, SMEM64);

    const int TB = 256;
    int nodeBlocks = (N_NODES + TB - 1) / TB;       // 391
    int edgeBlocks = (N_EDGES + TB - 1) / TB;       // 6250
    int scanBlocks = (N_NODES + 1023) / 1024;       // 98
    int gemmBlocks = (N_NODES + 127) / 128;         // 782
    int gatherBlocks = (N_NODES + 7) / 8;           // 12500 (8 warps / block)

    // degrees + norms
    zero_deg_kernel<<<nodeBlocks, TB>>>();
    count_deg_kernel<<<edgeBlocks, TB>>>(src, dst);
    norms_kernel<<<nodeBlocks, TB>>>();

    // CSR by dst
    scan1_kernel<<<scanBlocks, 1024>>>();
    scan2_kernel<<<1, 128>>>(scanBlocks);
    scan3_kernel<<<nodeBlocks, TB>>>();
    csr_fill_kernel<<<edgeBlocks, TB>>>(src, dst);

    // layer 0: feat(128) -> h(128), relu
    mma_gemm_kernel<128><<<gemmBlocks, TB, SMEM128>>>(feat, W0, t16);
    gather_kernel<4, true><<<gatherBlocks, TB>>>(t16, b0, h_ptr);

    // layer 1: h(128) -> h(128), relu
    mma_gemm_kernel<128><<<gemmBlocks, TB, SMEM128>>>(h_ptr, W1, t16);
    gather_kernel<4, true><<<gatherBlocks, TB>>>(t16, b1, h_ptr);

    // layer 2: h(128) -> out(64), no relu
    mma_gemm_kernel<64><<<gemmBlocks, TB, SMEM64>>>(h_ptr, W2, t16);
    gather_kernel<2, false><<<gatherBlocks, TB>>>(t16, b2, out);
}